// round 17
// baseline (speedup 1.0000x reference)
#include <cuda_runtime.h>
#include <cuda_bf16.h>
#include <cstdint>

#define DEV_INLINE __device__ __forceinline__
typedef unsigned long long u64;

static constexpr int V  = 32000;
static constexpr int H  = 512;
static constexpr int Bz = 64;
static constexpr int S  = 128;
static constexpr int H2 = 1024;
static constexpr int G4 = 2048;
static constexpr int G8 = 4096;
static constexpr int R  = S * Bz;

// ---------------- scratch ---------------------------------------------------
__device__ float g_GF  [R * G4];
__device__ float g_GB  [R * G4];
__device__ float g_G1  [R * G8];
__device__ __align__(16) __nv_bfloat16 g_Xs  [2][R * H];
__device__ __align__(16) __nv_bfloat16 g_XINs[2][R * H2];
__device__ __align__(16) __nv_bfloat16 g_WFs[2][G4 * H];
__device__ __align__(16) __nv_bfloat16 g_WBs[2][G4 * H];
__device__ __align__(16) __nv_bfloat16 g_W1s[2][G8 * H2];
__device__ __align__(16) __nv_bfloat16 g_WLs[2][(size_t)V * H2];
__device__ __align__(16) __nv_bfloat16 g_H2Rs[2][128 * H2];
__device__ __align__(16) __nv_bfloat16 g_Wb [3][128][2][32][1024];
__device__ __align__(16) __nv_bfloat16 g_Wb0[2][64][2][32][512];
__device__ __align__(16) __nv_bfloat16 g_H1s[2][2][Bz][H2];
__device__ __align__(16) __nv_bfloat16 g_H2s[2][2][Bz][H2];
__device__ __align__(16) __nv_bfloat16 g_L0s[2][2][2][Bz][H];
__device__ unsigned g_bar0[2];
__device__ unsigned g_bar1;

// ---------------- helpers ---------------------------------------------------
DEV_INLINE u64 pk2(float x, float y) {
    u64 r; asm("mov.b64 %0, {%1, %2};" : "=l"(r) : "f"(x), "f"(y)); return r;
}
DEV_INLINE float2 upk2(u64 v) {
    float2 r; asm("mov.b64 {%0, %1}, %2;" : "=f"(r.x), "=f"(r.y) : "l"(v)); return r;
}
#define FMA2(d, a, b) asm("fma.rn.f32x2 %0, %1, %2, %0;" : "+l"(d) : "l"(a), "l"(b))
DEV_INLINE float sigf(float x) { return 1.f / (1.f + expf(-x)); }

DEV_INLINE uint32_t smem_u32(const void* p) {
    uint32_t a;
    asm("{ .reg .u64 t; cvta.to.shared.u64 t, %1; cvt.u32.u64 %0, t; }" : "=r"(a) : "l"(p));
    return a;
}
DEV_INLINE void cpa16(uint32_t dst, const void* src) {
    asm volatile("cp.async.cg.shared.global [%0], [%1], 16;" :: "r"(dst), "l"(src) : "memory");
}
#define CP_COMMIT() asm volatile("cp.async.commit_group;" ::: "memory")
template <int N> DEV_INLINE void cp_wait() {
    asm volatile("cp.async.wait_group %0;" :: "n"(N) : "memory");
}
DEV_INLINE void ldsm_x4(uint32_t& a0, uint32_t& a1, uint32_t& a2, uint32_t& a3, uint32_t ad) {
    asm volatile("ldmatrix.sync.aligned.m8n8.x4.shared.b16 {%0,%1,%2,%3}, [%4];"
                 : "=r"(a0), "=r"(a1), "=r"(a2), "=r"(a3) : "r"(ad));
}
DEV_INLINE void ldsm_x2(uint32_t& b0, uint32_t& b1, uint32_t ad) {
    asm volatile("ldmatrix.sync.aligned.m8n8.x2.shared.b16 {%0,%1}, [%2];"
                 : "=r"(b0), "=r"(b1) : "r"(ad));
}
DEV_INLINE void mma16816(float* c, uint32_t a0, uint32_t a1, uint32_t a2, uint32_t a3,
                         uint32_t b0, uint32_t b1) {
    asm volatile("mma.sync.aligned.m16n8k16.row.col.f32.bf16.bf16.f32 "
                 "{%0,%1,%2,%3}, {%4,%5,%6,%7}, {%8,%9}, {%0,%1,%2,%3};"
                 : "+f"(c[0]), "+f"(c[1]), "+f"(c[2]), "+f"(c[3])
                 : "r"(a0), "r"(a1), "r"(a2), "r"(a3), "r"(b0), "r"(b1));
}
DEV_INLINE void splitw(float v, __nv_bfloat16& hi, __nv_bfloat16& lo) {
    hi = __float2bfloat16(v);
    lo = __float2bfloat16(v - __bfloat162float(hi));
}

// ---------------- small kernels ----------------------------------------------
__global__ void k_embed(const int* __restrict__ x, const float* __restrict__ emb) {
    int r = blockIdx.x;
    int tok = x[r];
    float4 v = make_float4(0.f, 0.f, 0.f, 0.f);
    if (tok != 0) v = *(const float4*)(emb + (size_t)tok * H + threadIdx.x * 4);
    size_t base = (size_t)r * H + threadIdx.x * 4;
    float vv[4] = {v.x, v.y, v.z, v.w};
#pragma unroll
    for (int i = 0; i < 4; i++) {
        __nv_bfloat16 hi, lo; splitw(vv[i], hi, lo);
        g_Xs[0][base + i] = hi;
        g_Xs[1][base + i] = lo;
    }
}

__global__ void k_prep_wih(const float* __restrict__ wih_f, const float* __restrict__ wih_b,
                           const float* __restrict__ wih1) {
    int r = blockIdx.x;
    const float* src; __nv_bfloat16 *dh, *dl; int K;
    if (r < 2048)      { src = wih_f + (size_t)r * H;  dh = &g_WFs[0][(size_t)r * H];  dl = &g_WFs[1][(size_t)r * H];  K = H; }
    else if (r < 4096) { int q = r - 2048; src = wih_b + (size_t)q * H;  dh = &g_WBs[0][(size_t)q * H];  dl = &g_WBs[1][(size_t)q * H];  K = H; }
    else               { int q = r - 4096; src = wih1 + (size_t)q * H2; dh = &g_W1s[0][(size_t)q * H2]; dl = &g_W1s[1][(size_t)q * H2]; K = H2; }
    for (int k = threadIdx.x; k < K; k += 256) {
        __nv_bfloat16 hi, lo; splitw(src[k], hi, lo);
        dh[k] = hi; dl[k] = lo;
    }
}

__global__ void k_prep_wlin(const float* __restrict__ wlin) {
    int r = blockIdx.x;
    const float* src = wlin + (size_t)r * H2;
    size_t o = (size_t)r * H2;
#pragma unroll
    for (int q = 0; q < 4; q++) {
        int k = threadIdx.x + q * 256;
        __nv_bfloat16 hi, lo; splitw(src[k], hi, lo);
        g_WLs[0][o + k] = hi;
        g_WLs[1][o + k] = lo;
    }
}

__global__ void k_prep_w(const float* __restrict__ whh1, const float* __restrict__ whh2,
                         const float* __restrict__ wih2) {
    int mr = blockIdx.x;
    int mat = mr >> 12, r = mr & 4095;
    const float* W = mat == 0 ? whh1 : (mat == 1 ? whh2 : wih2);
    int g = r >> 10, jglob = r & 1023;
    int bx = jglob >> 3, gr = g * 8 + (jglob & 7);
    const float* src = W + (size_t)r * H2;
#pragma unroll
    for (int q = 0; q < 4; q++) {
        int k = threadIdx.x + q * 256;
        __nv_bfloat16 hi, lo; splitw(src[k], hi, lo);
        g_Wb[mat][bx][0][gr][k] = hi;
        g_Wb[mat][bx][1][gr][k] = lo;
    }
}

__global__ void k_prep_w0(const float* __restrict__ whh_f, const float* __restrict__ whh_b) {
    int mr = blockIdx.x;
    int dir = mr >> 11, r = mr & 2047;
    const float* W = dir ? whh_b : whh_f;
    int g = r >> 9, j = r & 511;
    int bx = j >> 3, gr = g * 8 + (j & 7);
    const float* src = W + (size_t)r * H;
#pragma unroll
    for (int q = 0; q < 2; q++) {
        int k = threadIdx.x + q * 256;
        __nv_bfloat16 hi, lo; splitw(src[k], hi, lo);
        g_Wb0[dir][bx][0][gr][k] = hi;
        g_Wb0[dir][bx][1][gr][k] = lo;
    }
}

__global__ void k_prep_h(const float* __restrict__ h01, const float* __restrict__ h02) {
    int i = blockIdx.x * 256 + threadIdx.x;
    int which = i >> 16, e = i & 65535;
    int b = e >> 10, k = e & 1023;
    __nv_bfloat16 hi, lo; splitw((which ? h02 : h01)[e], hi, lo);
    if (which) { g_H2s[0][0][b][k] = hi; g_H2s[0][1][b][k] = lo; }
    else       { g_H1s[0][0][b][k] = hi; g_H1s[0][1][b][k] = lo; }
}

__global__ void k_prep_h0(const float* __restrict__ h0f, const float* __restrict__ h0b) {
    int i = blockIdx.x * 256 + threadIdx.x;
    if (i == 0) { g_bar0[0] = 0u; g_bar0[1] = 0u; g_bar1 = 0u; }
    g_H2Rs[0][65536 + i] = __float2bfloat16(0.f);
    g_H2Rs[1][65536 + i] = __float2bfloat16(0.f);
    int dir = i >> 15, e = i & 32767;
    int b = e >> 9, k = e & 511;
    __nv_bfloat16 hi, lo; splitw((dir ? h0b : h0f)[e], hi, lo);
    g_L0s[dir][0][0][b][k] = hi;
    g_L0s[dir][0][1][b][k] = lo;
}

// ---------------- batched split-bf16 HMMA GEMM (phases B, D, F) ---------------
template <int K>
DEV_INLINE void ldc_g(uint32_t smb, int buf,
                      const char* Ahi, const char* Alo,
                      const char* Whi, const char* Wlo,
                      int bm, int bn, int c, int tid) {
#pragma unroll
    for (int q = 0; q < 8; q++) {
        int i = tid + q * 256;
        int sp = (i & 1023) >> 9, rem = i & 511, row = rem >> 2, sg = rem & 3;
        if (i < 1024) {
            const char* src = (sp ? Alo : Ahi) + (size_t)(bm + row) * (K * 2) + c * 64 + sg * 16;
            cpa16(smb + buf * 20480 + sp * 10240 + row * 80 + sg * 16, src);
        } else {
            const char* src = (sp ? Wlo : Whi) + (size_t)(bn + row) * (K * 2) + c * 64 + sg * 16;
            cpa16(smb + 40960 + buf * 20480 + sp * 10240 + row * 80 + sg * 16, src);
        }
    }
    CP_COMMIT();
}

template <int K>
__global__ void __launch_bounds__(256, 2) k_gemm_hmma(
        const __nv_bfloat16* __restrict__ Ahi, const __nv_bfloat16* __restrict__ Alo,
        const __nv_bfloat16* __restrict__ Whi, const __nv_bfloat16* __restrict__ Wlo,
        const float* __restrict__ b1, const float* __restrict__ b2,
        float* __restrict__ C, int N, int Mvalid) {
    extern __shared__ char smc[];
    uint32_t smb = smem_u32(smc);
    float* bsum = (float*)(smc + 81920);
    const int tid = threadIdx.x, w = tid >> 5, l = tid & 31;
    const int bm = blockIdx.y * 128, bn = blockIdx.x * 128;
    const int m0w = (w & 3) * 32, n0w = (w >> 2) * 64;

    if (tid < 128) bsum[tid] = b1[bn + tid] + (b2 ? b2[bn + tid] : 0.f);

    float acc[2][8][4];
#pragma unroll
    for (int mt = 0; mt < 2; mt++)
#pragma unroll
        for (int nf = 0; nf < 8; nf++)
#pragma unroll
            for (int i = 0; i < 4; i++) acc[mt][nf][i] = 0.f;

    ldc_g<K>(smb, 0, (const char*)Ahi, (const char*)Alo,
             (const char*)Whi, (const char*)Wlo, bm, bn, 0, tid);
    constexpr int NCH = K / 32;
    for (int c = 0; c < NCH; c++) {
        if (c < NCH - 1) {
            ldc_g<K>(smb, (c + 1) & 1, (const char*)Ahi, (const char*)Alo,
                     (const char*)Whi, (const char*)Wlo, bm, bn, c + 1, tid);
            cp_wait<1>();
        } else cp_wait<0>();
        __syncthreads();
        uint32_t ab = smb + (c & 1) * 20480;
        uint32_t wb = smb + 40960 + (c & 1) * 20480;
#pragma unroll
        for (int ks = 0; ks < 2; ks++) {
            uint32_t ah[2][4], al[2][4];
#pragma unroll
            for (int mt = 0; mt < 2; mt++) {
                uint32_t aa = ab + (uint32_t)(m0w + mt * 16 + (l & 15)) * 80 + (l >> 4) * 16 + ks * 32;
                ldsm_x4(ah[mt][0], ah[mt][1], ah[mt][2], ah[mt][3], aa);
                ldsm_x4(al[mt][0], al[mt][1], al[mt][2], al[mt][3], aa + 10240);
            }
#pragma unroll
            for (int nf = 0; nf < 8; nf++) {
                uint32_t bb = wb + (uint32_t)(n0w + nf * 8 + (l & 7)) * 80 + ((l >> 3) & 1) * 16 + ks * 32;
                uint32_t bh0, bh1, bl0, bl1;
                ldsm_x2(bh0, bh1, bb);
                ldsm_x2(bl0, bl1, bb + 10240);
#pragma unroll
                for (int mt = 0; mt < 2; mt++) {
                    mma16816(acc[mt][nf], ah[mt][0], ah[mt][1], ah[mt][2], ah[mt][3], bh0, bh1);
                    mma16816(acc[mt][nf], al[mt][0], al[mt][1], al[mt][2], al[mt][3], bh0, bh1);
                    mma16816(acc[mt][nf], ah[mt][0], ah[mt][1], ah[mt][2], ah[mt][3], bl0, bl1);
                }
            }
        }
        __syncthreads();
    }
#pragma unroll
    for (int mt = 0; mt < 2; mt++) {
        int row = bm + m0w + mt * 16 + (l >> 2);
#pragma unroll
        for (int nf = 0; nf < 8; nf++) {
            int lc = n0w + nf * 8 + (l & 3) * 2;
            float bs0 = bsum[lc], bs1 = bsum[lc + 1];
            if (row < Mvalid)
                *(float2*)(C + (size_t)row * N + bn + lc) =
                    make_float2(acc[mt][nf][0] + bs0, acc[mt][nf][1] + bs1);
            if (row + 8 < Mvalid)
                *(float2*)(C + (size_t)(row + 8) * N + bn + lc) =
                    make_float2(acc[mt][nf][2] + bs0, acc[mt][nf][3] + bs1);
        }
    }
}

// ---------------- shared recurrent HMMA constants (chunk k=256) ----------------
static constexpr int RS   = 528;
static constexpr int HSPL = 64 * RS;
static constexpr int HBUF = 2 * HSPL;
static constexpr int WBASE = 2 * HBUF;
static constexpr int WSPL = 32 * RS;
static constexpr int WBUF = 2 * WSPL;
static constexpr int EXOFF = WBASE + 2 * WBUF;  // total 211968 B

// l0: single-shot H load (both chunks, one group)
DEV_INLINE void load_h_l0_full(uint32_t smb, const char* Hsrc, int tid) {
#pragma unroll
    for (int q = 0; q < 32; q++) {
        int i = tid + q * 256;                 // [0, 8192)
        int c = i >> 12, rem = i & 4095;
        int sp = rem >> 11, r2 = rem & 2047, row = r2 >> 5, sg = r2 & 31;
        cpa16(smb + c * HBUF + sp * HSPL + row * RS + sg * 16,
              Hsrc + (size_t)sp * (64 * 1024) + row * 1024 + c * 512 + sg * 16);
    }
    CP_COMMIT();
}

// l1: split loaders (W-only / H-only / combined)
DEV_INLINE void load_W_l1(uint32_t smb, int buf, const char* Wsrc, int c, int tid) {
#pragma unroll
    for (int q = 0; q < 8; q++) {
        int jj = tid + q * 256;                // [0, 2048)
        int sp = jj >> 10, rem = jj & 1023, row = rem >> 5, sg = rem & 31;
        cpa16(smb + WBASE + buf * WBUF + sp * WSPL + row * RS + sg * 16,
              Wsrc + (size_t)sp * (32 * 2048) + row * 2048 + c * 512 + sg * 16);
    }
    CP_COMMIT();
}
DEV_INLINE void load_H_l1(uint32_t smb, int buf, const char* Hsrc, int c, int tid) {
#pragma unroll
    for (int q = 0; q < 16; q++) {
        int i = tid + q * 256;                 // [0, 4096)
        int sp = i >> 11, rem = i & 2047, row = rem >> 5, sg = rem & 31;
        cpa16(smb + buf * HBUF + sp * HSPL + row * RS + sg * 16,
              Hsrc + (size_t)sp * (64 * 2048) + row * 2048 + c * 512 + sg * 16);
    }
    CP_COMMIT();
}
DEV_INLINE void load_chunk_l1(uint32_t smb, int buf, const char* Wsrc, const char* Hsrc,
                              int c, int tid) {
#pragma unroll
    for (int q = 0; q < 24; q++) {
        int i = tid + q * 256;
        if (i < 4096) {
            int sp = i >> 11, rem = i & 2047, row = rem >> 5, sg = rem & 31;
            cpa16(smb + buf * HBUF + sp * HSPL + row * RS + sg * 16,
                  Hsrc + (size_t)sp * (64 * 2048) + row * 2048 + c * 512 + sg * 16);
        } else {
            int jj = i - 4096, sp = jj >> 10, rem = jj & 1023, row = rem >> 5, sg = rem & 31;
            cpa16(smb + WBASE + buf * WBUF + sp * WSPL + row * RS + sg * 16,
                  Wsrc + (size_t)sp * (32 * 2048) + row * 2048 + c * 512 + sg * 16);
        }
    }
    CP_COMMIT();
}

// generic 16-ks compute over one resident chunk
DEV_INLINE void compute_chunk(uint32_t hb, uint32_t wb, float* acc0, float* acc1,
                              uint32_t aoff, int n0, int brow, uint32_t bko) {
#pragma unroll
    for (int ks = 0; ks < 16; ks++) {
        uint32_t a0, a1, a2, a3, l0r, l1r, l2r, l3r;
        ldsm_x4(a0, a1, a2, a3, hb + aoff + ks * 32);
        ldsm_x4(l0r, l1r, l2r, l3r, hb + HSPL + aoff + ks * 32);
#pragma unroll
        for (int nt = 0; nt < 2; nt++) {
            uint32_t bh0, bh1, bl0, bl1;
            uint32_t bb = wb + (uint32_t)(n0 + nt * 8 + brow) * RS + bko + ks * 32;
            ldsm_x2(bh0, bh1, bb);
            ldsm_x2(bl0, bl1, bb + WSPL);
            float* ac = nt ? acc1 : acc0;
            mma16816(ac, a0, a1, a2, a3, bh0, bh1);
            mma16816(ac, l0r, l1r, l2r, l3r, bh0, bh1);
            mma16816(ac, a0, a1, a2, a3, bl0, bl1);
        }
    }
}

DEV_INLINE void store_frag(float* Ex, int m0, int n0, int l, const float* ac0, const float* ac1) {
#pragma unroll
    for (int nt = 0; nt < 2; nt++) {
        const float* ac = nt ? ac1 : ac0;
        int er = m0 + (l >> 2), ec = n0 + nt * 8 + (l & 3) * 2;
        Ex[er * 36 + ec] = ac[0];       Ex[er * 36 + ec + 1] = ac[1];
        Ex[(er + 8) * 36 + ec] = ac[2]; Ex[(er + 8) * 36 + ec + 1] = ac[3];
    }
}

// ---------------- HMMA layer-0 (W resident; single-shot H; pg in barrier) -----
__global__ void __launch_bounds__(256, 1) k_l0_hmma(
        const float* __restrict__ c0f, const float* __restrict__ c0b) {
    extern __shared__ char smc[];
    uint32_t smb = smem_u32(smc);
    float* Ex = (float*)(smc + EXOFF);
    const int tid = threadIdx.x, w = tid >> 5, l = tid & 31;
    const int dir = blockIdx.x >> 6, jb = blockIdx.x & 63;
    const int m0 = (w & 3) * 16, n0 = (w >> 2) * 16;
    const uint32_t aoff = (uint32_t)((m0 + (l & 15)) * RS + (l >> 4) * 16);
    const int brow = l & 7;
    const uint32_t bko = (uint32_t)(((l >> 3) & 1) * 16);
    const int j = tid & 7, b0 = tid >> 3;
    const int jglob = jb * 8 + j;
    const float* preB = dir ? g_GB : g_GF;
    const float* c0   = dir ? c0b  : c0f;
    const char* Wsrc = (const char*)&g_Wb0[dir][jb][0][0][0];

    // preload BOTH W chunk-images into resident SMEM
#pragma unroll
    for (int q = 0; q < 16; q++) {
        int i = tid + q * 256;
        int c = i >> 11, rem = i & 2047;
        int sp = rem >> 10, r2 = rem & 1023, row = r2 >> 5, sg = r2 & 31;
        cpa16(smb + WBASE + c * WBUF + sp * WSPL + row * RS + sg * 16,
              Wsrc + (size_t)sp * (32 * 1024) + row * 1024 + c * 512 + sg * 16);
    }
    CP_COMMIT();

    float cst[2] = { c0[b0 * H + jglob], c0[(b0 + 32) * H + jglob] };

    // prefetch pre-gates for t=0
    float pg[2][4];
    {
        const float* pre = preB + (size_t)(dir ? (S - 1) : 0) * Bz * G4;
#pragma unroll
        for (int r = 0; r < 2; r++) {
            const float* pb = pre + (size_t)(b0 + r * 32) * G4;
            pg[r][0] = __ldg(pb + 0 * H + jglob); pg[r][1] = __ldg(pb + 1 * H + jglob);
            pg[r][2] = __ldg(pb + 2 * H + jglob); pg[r][3] = __ldg(pb + 3 * H + jglob);
        }
    }
    cp_wait<0>();
    __syncthreads();

    for (int t = 0; t < S; t++) {
        int p = t & 1;
        const char* Hsrc = (const char*)&g_L0s[dir][p][0][0][0];
        load_h_l0_full(smb, Hsrc, tid);
        cp_wait<0>();
        __syncthreads();
        float acc0[4] = {0, 0, 0, 0}, acc1[4] = {0, 0, 0, 0};
#pragma unroll
        for (int c = 0; c < 2; c++)
            compute_chunk(smb + c * HBUF, smb + WBASE + c * WBUF,
                          acc0, acc1, aoff, n0, brow, bko);
        store_frag(Ex, m0, n0, l, acc0, acc1);
        __syncthreads();
#pragma unroll
        for (int r = 0; r < 2; r++) {
            int b = b0 + r * 32;
            float gi = Ex[b * 36 + j]      + pg[r][0];
            float gf = Ex[b * 36 + 8 + j]  + pg[r][1];
            float gg = Ex[b * 36 + 16 + j] + pg[r][2];
            float go = Ex[b * 36 + 24 + j] + pg[r][3];
            float c2 = sigf(gf) * cst[r] + sigf(gi) * tanhf(gg);
            cst[r] = c2;
            float h = sigf(go) * tanhf(c2);
            __nv_bfloat16 hi, lo; splitw(h, hi, lo);
            size_t xe = ((size_t)t * Bz + b) * H2 + dir * H + jglob;
            g_XINs[0][xe] = hi;
            g_XINs[1][xe] = lo;
            g_L0s[dir][p ^ 1][0][b][jglob] = hi;
            g_L0s[dir][p ^ 1][1][b][jglob] = lo;
        }
        // barrier (arrive -> pg prefetch for t+1 -> poll)
        __threadfence();
        __syncthreads();
        if (tid == 0) atomicAdd(&g_bar0[dir], 1u);
        if (t + 1 < S) {
            const float* pre = preB + (size_t)(dir ? (S - 2 - t) : (t + 1)) * Bz * G4;
#pragma unroll
            for (int r = 0; r < 2; r++) {
                const float* pb = pre + (size_t)(b0 + r * 32) * G4;
                pg[r][0] = __ldg(pb + 0 * H + jglob); pg[r][1] = __ldg(pb + 1 * H + jglob);
                pg[r][2] = __ldg(pb + 2 * H + jglob); pg[r][3] = __ldg(pb + 3 * H + jglob);
            }
        }
        if (tid == 0)
            while (*(volatile unsigned*)&g_bar0[dir] < 64u * (t + 1)) __nanosleep(32);
        __syncthreads();
    }
}

// ---------------- HMMA layer-1 (pg + W-fill hidden in barrier) -----------------
__global__ void __launch_bounds__(256, 1) k_l1_hmma(
        const float* __restrict__ c02,
        const float* __restrict__ bih2, const float* __restrict__ bhh2) {
    extern __shared__ char smc[];
    uint32_t smb = smem_u32(smc);
    float* Ex = (float*)(smc + EXOFF);
    const int tid = threadIdx.x, w = tid >> 5, l = tid & 31, bx = blockIdx.x;
    const int m0 = (w & 3) * 16, n0 = (w >> 2) * 16;
    const uint32_t aoff = (uint32_t)((m0 + (l & 15)) * RS + (l >> 4) * 16);
    const int brow = l & 7;
    const uint32_t bko = (uint32_t)(((l >> 3) & 1) * 16);
    const int j = tid & 7, b0 = tid >> 3;
    const int jglob = bx * 8 + j;

    float c2[2] = { c02[b0 * H2 + jglob], c02[(b0 + 32) * H2 + jglob] };
    float bsr[4];
#pragma unroll
    for (int g = 0; g < 4; g++) bsr[g] = bih2[g * H2 + jglob] + bhh2[g * H2 + jglob];

    // prefetch G1 pre-gates for t=0
    float pg[2][4];
#pragma unroll
    for (int r = 0; r < 2; r++) {
        const float* pb = g_G1 + ((size_t)(b0 + r * 32)) * G8;
        pg[r][0] = __ldg(pb + 0 * H2 + jglob); pg[r][1] = __ldg(pb + 1 * H2 + jglob);
        pg[r][2] = __ldg(pb + 2 * H2 + jglob); pg[r][3] = __ldg(pb + 3 * H2 + jglob);
    }

    for (int t = 0; t < S; t++) {
        int p = t & 1;
        // ---- lstm1: whh1 @ h1prev (4-chunk pipeline) ----
        float acc0[4] = {0, 0, 0, 0}, acc1[4] = {0, 0, 0, 0};
        {
            const char* W0 = (const char*)&g_Wb[0][bx][0][0][0];
            const char* H0 = (const char*)&g_H1s[p][0][0][0];
            load_chunk_l1(smb, 0, W0, H0, 0, tid);
            for (int c = 0; c < 4; c++) {
                if (c < 3) { load_chunk_l1(smb, (c + 1) & 1, W0, H0, c + 1, tid); cp_wait<1>(); }
                else cp_wait<0>();
                __syncthreads();
                compute_chunk(smb + (c & 1) * HBUF, smb + WBASE + (c & 1) * WBUF,
                              acc0, acc1, aoff, n0, brow, bko);
                __syncthreads();
            }
        }
        store_frag(Ex, m0, n0, l, acc0, acc1);
        __syncthreads();
#pragma unroll
        for (int r = 0; r < 2; r++) {
            int b = b0 + r * 32;
            float gi = Ex[b * 36 + j]      + pg[r][0];
            float gf = Ex[b * 36 + 8 + j]  + pg[r][1];
            float gg = Ex[b * 36 + 16 + j] + pg[r][2];
            float go = Ex[b * 36 + 24 + j] + pg[r][3];
            float cc = sigf(gf) * c2[r] + sigf(gi) * tanhf(gg);
            float h1 = sigf(go) * tanhf(cc);
            __nv_bfloat16 hi, lo; splitw(h1, hi, lo);
            g_H1s[p ^ 1][0][b][jglob] = hi;
            g_H1s[p ^ 1][1][b][jglob] = lo;
        }
        // pre-issue the W-half of lstm2 chunk0 (read-only, always safe)
        load_W_l1(smb, 0, (const char*)&g_Wb[1][bx][0][0][0], 0, tid);
        // barrier (arrive -> pg prefetch for t+1 -> poll)
        __threadfence();
        __syncthreads();
        if (tid == 0) atomicAdd(&g_bar1, 1u);
        if (t + 1 < S) {
#pragma unroll
            for (int r = 0; r < 2; r++) {
                const float* pb = g_G1 + ((size_t)(t + 1) * Bz + b0 + r * 32) * G8;
                pg[r][0] = __ldg(pb + 0 * H2 + jglob); pg[r][1] = __ldg(pb + 1 * H2 + jglob);
                pg[r][2] = __ldg(pb + 2 * H2 + jglob); pg[r][3] = __ldg(pb + 3 * H2 + jglob);
            }
        }
        if (tid == 0)
            while (*(volatile unsigned*)&g_bar1 < 128u * (t + 1)) __nanosleep(32);
        __syncthreads();

        // ---- lstm2: fused 8-chunk pass (whh2@h2prev, then wih2@h1new) ----
        acc0[0] = acc0[1] = acc0[2] = acc0[3] = 0.f;
        acc1[0] = acc1[1] = acc1[2] = acc1[3] = 0.f;
        {
            const char* W0 = (const char*)&g_Wb[1][bx][0][0][0];
            const char* H0 = (const char*)&g_H2s[p][0][0][0];
            const char* W1 = (const char*)&g_Wb[2][bx][0][0][0];
            const char* H1n = (const char*)&g_H1s[p ^ 1][0][0][0];
            load_H_l1(smb, 0, H0, 0, tid);      // W-half already in flight
            for (int c = 0; c < 8; c++) {
                if (c < 7) {
                    int cn = c + 1;
                    load_chunk_l1(smb, cn & 1, (cn < 4) ? W0 : W1, (cn < 4) ? H0 : H1n,
                                  cn & 3, tid);
                    cp_wait<1>();
                } else cp_wait<0>();
                __syncthreads();
                compute_chunk(smb + (c & 1) * HBUF, smb + WBASE + (c & 1) * WBUF,
                              acc0, acc1, aoff, n0, brow, bko);
                __syncthreads();
            }
        }
        store_frag(Ex, m0, n0, l, acc0, acc1);
        __syncthreads();
#pragma unroll
        for (int r = 0; r < 2; r++) {
            int b = b0 + r * 32;
            float gi = Ex[b * 36 + j]      + bsr[0];
            float gf = Ex[b * 36 + 8 + j]  + bsr[1];
            float gg = Ex[b * 36 + 16 + j] + bsr[2];
            float go = Ex[b * 36 + 24 + j] + bsr[3];
            float cn = sigf(gf) * c2[r] + sigf(gi) * tanhf(gg);
            c2[r] = cn;
            float h2 = sigf(go) * tanhf(cn);
            __nv_bfloat16 hi, lo; splitw(h2, hi, lo);
            g_H2s[p ^ 1][0][b][jglob] = hi;
            g_H2s[p ^ 1][1][b][jglob] = lo;
            if (t == S - 1) {
                g_H2Rs[0][(size_t)b * H2 + jglob] = hi;
                g_H2Rs[1][(size_t)b * H2 + jglob] = lo;
            }
        }
        __syncthreads();
    }
}

// ---------------- launch -----------------------------------------------------
extern "C" void kernel_launch(void* const* d_in, const int* in_sizes, int n_in,
                              void* d_out, int out_size) {
    const int*   x     = (const int*)  d_in[0];
    const float* emb   = (const float*)d_in[1];
    const float* h0f   = (const float*)d_in[2];
    const float* c0f   = (const float*)d_in[3];
    const float* h0b   = (const float*)d_in[4];
    const float* c0b   = (const float*)d_in[5];
    const float* h01   = (const float*)d_in[6];
    const float* h02   = (const float*)d_in[7];
    const float* c02   = (const float*)d_in[8];
    const float* wih_f = (const float*)d_in[9];
    const float* whh_f = (const float*)d_in[10];
    const float* bih_f = (const float*)d_in[11];
    const float* bhh_f = (const float*)d_in[12];
    const float* wih_b = (const float*)d_in[13];
    const float* whh_b = (const float*)d_in[14];
    const float* bih_b = (const float*)d_in[15];
    const float* bhh_b = (const float*)d_in[16];
    const float* wih1  = (const float*)d_in[17];
    const float* whh1  = (const float*)d_in[18];
    const float* bih1  = (const float*)d_in[19];
    const float* bhh1  = (const float*)d_in[20];
    const float* wih2  = (const float*)d_in[21];
    const float* whh2  = (const float*)d_in[22];
    const float* bih2  = (const float*)d_in[23];
    const float* bhh2  = (const float*)d_in[24];
    const float* wlin  = (const float*)d_in[25];
    const float* blin  = (const float*)d_in[26];
    float* out = (float*)d_out;

    float *pGF, *pGB, *pG1;
    cudaGetSymbolAddress((void**)&pGF, g_GF);
    cudaGetSymbolAddress((void**)&pGB, g_GB);
    cudaGetSymbolAddress((void**)&pG1, g_G1);
    __nv_bfloat16 *pXs, *pXINs, *pWF, *pWB, *pW1, *pWL, *pH2Rs;
    cudaGetSymbolAddress((void**)&pXs,   g_Xs);
    cudaGetSymbolAddress((void**)&pXINs, g_XINs);
    cudaGetSymbolAddress((void**)&pWF,   g_WFs);
    cudaGetSymbolAddress((void**)&pWB,   g_WBs);
    cudaGetSymbolAddress((void**)&pW1,   g_W1s);
    cudaGetSymbolAddress((void**)&pWL,   g_WLs);
    cudaGetSymbolAddress((void**)&pH2Rs, g_H2Rs);

    const int HM_SM = 211968;
    const int GM_SM = 82432;
    cudaFuncSetAttribute(k_l0_hmma, cudaFuncAttributeMaxDynamicSharedMemorySize, HM_SM);
    cudaFuncSetAttribute(k_l1_hmma, cudaFuncAttributeMaxDynamicSharedMemorySize, HM_SM);
    cudaFuncSetAttribute(k_gemm_hmma<512>,  cudaFuncAttributeMaxDynamicSharedMemorySize, GM_SM);
    cudaFuncSetAttribute(k_gemm_hmma<1024>, cudaFuncAttributeMaxDynamicSharedMemorySize, GM_SM);

    // A: gather (split) + prep splits (also zeroes barriers + h2 pad each replay)
    k_embed<<<R, 128>>>(x, emb);
    k_prep_h0<<<256, 256>>>(h0f, h0b);
    k_prep_h<<<512, 256>>>(h01, h02);
    k_prep_w0<<<2 * 2048, 256>>>(whh_f, whh_b);
    k_prep_w<<<3 * 4096, 256>>>(whh1, whh2, wih2);
    k_prep_wih<<<8192, 256>>>(wih_f, wih_b, wih1);
    k_prep_wlin<<<V, 256>>>(wlin);

    // B: hoisted input-side gate GEMMs for layer 0 (HMMA)
    k_gemm_hmma<512><<<dim3(G4 / 128, R / 128), 256, GM_SM>>>(
        pXs, pXs + (size_t)R * H, pWF, pWF + (size_t)G4 * H, bih_f, bhh_f, pGF, G4, R);
    k_gemm_hmma<512><<<dim3(G4 / 128, R / 128), 256, GM_SM>>>(
        pXs, pXs + (size_t)R * H, pWB, pWB + (size_t)G4 * H, bih_b, bhh_b, pGB, G4, R);

    // C: HMMA persistent bidirectional layer-0 recurrence
    k_l0_hmma<<<128, 256, HM_SM>>>(c0f, c0b);

    // D: hoisted input-side GEMM for lstm1 (HMMA)
    k_gemm_hmma<1024><<<dim3(G8 / 128, R / 128), 256, GM_SM>>>(
        pXINs, pXINs + (size_t)R * H2, pW1, pW1 + (size_t)G8 * H2, bih1, bhh1, pG1, G8, R);

    // E: HMMA persistent layer-1 recurrence
    k_l1_hmma<<<128, 256, HM_SM>>>(c02, bih2, bhh2);

    // F: logits (HMMA, padded M=128, valid M=64)
    k_gemm_hmma<1024><<<dim3(V / 128, 1), 256, GM_SM>>>(
        pH2Rs, pH2Rs + (size_t)128 * H2, pWL, pWL + (size_t)V * H2,
        blin, nullptr, out, V, Bz);
}